// round 14
// baseline (speedup 1.0000x reference)
#include <cuda_runtime.h>
#include <math.h>

typedef unsigned int u32;
typedef unsigned short u16;
typedef unsigned long long u64;

#define BB 16
#define TT 4096
#define DM 1024
#define DP 64
#define NC 4
#define NTOK (BB*TT)            // 65536

// output layout (flat fp32, tuple order)
#define OUT_OFF    0ull
#define USTD_OFF   67108864ull
#define TEMP_OFF   67174400ull
#define ATTN_OFF   67174401ull
#define ORTHO_OFF  67436545ull
#define GEO_OFF    67436546ull
#define LATENT_OFF 67436547ull

#define NCHUNK 32
#define SCHUNK (TT/NCHUNK)      // 128

// scratch
__device__ float g_ps[BB*NCHUNK*DM];          // partial sums
__device__ float g_pq[BB*NCHUNK*DM];          // partial sumsq
__device__ float g_mean[BB*DM];
__device__ float g_rs[BB*DM];
__device__ u16   g_Xh[(size_t)NTOK*DM];       // bf16 hi of raw x
__device__ u16   g_Xl[(size_t)NTOK*DM];       // bf16 lo of raw x
__device__ u16   g_Wph[(size_t)BB*DM*DP];     // bf16 hi of rs*Wp
__device__ u16   g_Wpl[(size_t)BB*DM*DP];     // bf16 lo
__device__ u16   g_Woh[DP*DM];                // bf16 (single plane)
__device__ float g_CWo[NC*DM];                // centroids @ Wo  [4][1024]
__device__ float g_qbias[BB*DP];
__device__ u16   g_Ob[(size_t)NTOK*DP];       // offset, bf16 single plane
__device__ float g_gate[NTOK];
__device__ float g_temp_sum;
__device__ float g_cos_sum;

__device__ __forceinline__ float wsum(float v){
#pragma unroll
    for (int m = 16; m; m >>= 1) v += __shfl_xor_sync(0xffffffffu, v, m);
    return v;
}
__device__ __forceinline__ float softplusf(float v){
    return (v > 20.f) ? v : log1pf(expf(v));
}
// pack: low half = bf16(x), high half = bf16(y)
__device__ __forceinline__ u32 bf2(float x, float y){
    u32 r; asm("cvt.rn.bf16x2.f32 %0, %1, %2;" : "=r"(r) : "f"(y), "f"(x)); return r;
}
__device__ __forceinline__ void split2(float x, float y, u32 &h, u32 &l){
    h = bf2(x, y);
    float xh = __uint_as_float(h << 16);
    float yh = __uint_as_float(h & 0xFFFF0000u);
    l = bf2(x - xh, y - yh);
}
__device__ __forceinline__ u32 sptr(const void* p){
    return (u32)__cvta_generic_to_shared(p);
}
__device__ __forceinline__ void cp16(u32 dst, const void* src){
    asm volatile("cp.async.cg.shared.global [%0], [%1], 16;" :: "r"(dst), "l"(src));
}
#define CP_COMMIT() asm volatile("cp.async.commit_group;" ::: "memory")
#define CP_WAIT1()  asm volatile("cp.async.wait_group 1;" ::: "memory")
__device__ __forceinline__ void ldm4(u32* r, u32 addr){
    asm volatile("ldmatrix.sync.aligned.m8n8.x4.shared.b16 {%0,%1,%2,%3}, [%4];"
        : "=r"(r[0]),"=r"(r[1]),"=r"(r[2]),"=r"(r[3]) : "r"(addr));
}
__device__ __forceinline__ void ldm4t(u32* r, u32 addr){
    asm volatile("ldmatrix.sync.aligned.m8n8.x4.trans.shared.b16 {%0,%1,%2,%3}, [%4];"
        : "=r"(r[0]),"=r"(r[1]),"=r"(r[2]),"=r"(r[3]) : "r"(addr));
}
__device__ __forceinline__ void mma16816(float* c, const u32* a, u32 b0, u32 b1){
    asm volatile("mma.sync.aligned.m16n8k16.row.col.f32.bf16.bf16.f32 "
        "{%0,%1,%2,%3},{%4,%5,%6,%7},{%8,%9},{%0,%1,%2,%3};"
        : "+f"(c[0]),"+f"(c[1]),"+f"(c[2]),"+f"(c[3])
        : "r"(a[0]),"r"(a[1]),"r"(a[2]),"r"(a[3]),"r"(b0),"r"(b1));
}

// ---------------- stats over T + bf16 split of raw x ----------------
__global__ __launch_bounds__(256) void k_stats(const float* __restrict__ x){
    int b = blockIdx.x;
    int chunk = blockIdx.y;
    int c4 = threadIdx.x*4;
    size_t row0 = (size_t)b*TT + (size_t)chunk*SCHUNK;
    const float* p = x + row0*DM + c4;
    u16* xh = g_Xh + row0*DM + c4;
    u16* xl = g_Xl + row0*DM + c4;
    float4 s = make_float4(0,0,0,0), s2 = make_float4(0,0,0,0);
#pragma unroll 4
    for (int t = 0; t < SCHUNK; t++){
        float4 v = *(const float4*)(p + (size_t)t*DM);
        s.x += v.x; s.y += v.y; s.z += v.z; s.w += v.w;
        s2.x += v.x*v.x; s2.y += v.y*v.y; s2.z += v.z*v.z; s2.w += v.w*v.w;
        u32 h0,l0,h1,l1;
        split2(v.x, v.y, h0, l0);
        split2(v.z, v.w, h1, l1);
        *(uint2*)(xh + (size_t)t*DM) = make_uint2(h0, h1);
        *(uint2*)(xl + (size_t)t*DM) = make_uint2(l0, l1);
    }
    size_t o = ((size_t)b*NCHUNK + chunk)*DM + c4;
    *(float4*)(g_ps + o) = s;
    *(float4*)(g_pq + o) = s2;
}

__global__ void k_finstats(){
    int i = blockIdx.x*256 + threadIdx.x;
    if (i < BB*DM){
        int b = i >> 10, d = i & (DM-1);
        float s = 0.f, s2 = 0.f;
        const float* ps = g_ps + (size_t)b*NCHUNK*DM + d;
        const float* pq = g_pq + (size_t)b*NCHUNK*DM + d;
#pragma unroll 8
        for (int c = 0; c < NCHUNK; c++){
            s += ps[(size_t)c*DM];
            s2 += pq[(size_t)c*DM];
        }
        float mean = s / (float)TT;
        float var = (s2 - s*mean) / (float)(TT - 1);
        var = fmaxf(var, 0.f);
        float sd = sqrtf(var) + 1e-5f;
        g_mean[i] = mean;
        g_rs[i] = 1.f / sd;
    }
    if (i == 0){ g_temp_sum = 0.f; g_cos_sum = 0.f; }
}

// ---------------- merged prew + prec ----------------
__global__ __launch_bounds__(256) void k_prewc(const float* __restrict__ Wp,
                                               const float* __restrict__ bp){
    if (blockIdx.x < 1024){
        int i = blockIdx.x*256 + threadIdx.x;
        int j4 = i & 15;
        int rem = i >> 4;
        int d = rem & (DM-1);
        float r = g_rs[rem];
        float4 w = *(const float4*)(Wp + (size_t)d*DP + j4*4);
        float4 o; o.x = w.x*r; o.y = w.y*r; o.z = w.z*r; o.w = w.w*r;
        u32 h0,l0,h1,l1;
        split2(o.x, o.y, h0, l0);
        split2(o.z, o.w, h1, l1);
        *(uint2*)(g_Wph + (size_t)rem*DP + j4*4) = make_uint2(h0, h1);
        *(uint2*)(g_Wpl + (size_t)rem*DP + j4*4) = make_uint2(l0, l1);
    } else {
        __shared__ float red[256];
        int b = blockIdx.x - 1024;
        int t = threadIdx.x;
        int j = t & 63, part = t >> 6;
        float s = 0.f;
        const float* mn = g_mean + b*DM;
        const float* rs = g_rs + b*DM;
#pragma unroll 8
        for (int d = part*256; d < part*256 + 256; d++)
            s += mn[d] * rs[d] * Wp[(size_t)d*DP + j];
        red[t] = s;
        __syncthreads();
        if (t < 64)
            g_qbias[b*DP + j] = bp[j] - (red[j] + red[j+64] + red[j+128] + red[j+192]);
    }
}

// Wo -> bf16 single plane
__global__ void k_prewo(const float* __restrict__ Wo){
    int i = blockIdx.x*256 + threadIdx.x;
    float4 w = *(const float4*)(Wo + (size_t)i*4);
    *(uint2*)(g_Woh + (size_t)i*4) = make_uint2(bf2(w.x, w.y), bf2(w.z, w.w));
}

// CWo[n][j] = sum_d cent[n][d] * Wo[d][j]
__global__ void k_precw(const float* __restrict__ cent, const float* __restrict__ Wo){
    int j = blockIdx.x*256 + threadIdx.x;
    float s0=0.f, s1=0.f, s2=0.f, s3=0.f;
#pragma unroll 8
    for (int d = 0; d < DP; d++){
        float w = Wo[(size_t)d*DM + j];
        s0 += cent[0*DP+d]*w;
        s1 += cent[1*DP+d]*w;
        s2 += cent[2*DP+d]*w;
        s3 += cent[3*DP+d]*w;
    }
    g_CWo[0*DM+j]=s0; g_CWo[1*DM+j]=s1; g_CWo[2*DM+j]=s2; g_CWo[3*DM+j]=s3;
}

// ---------------- FUSED GEMM1 + token math, cp.async pipeline ----------------
// CTA: 128 tok x 64 n. K chunks of 32, 3-stage cp.async pipeline. 8 warps 4m x 2n.
#define A1_ST 40
#define B1_ST 72
// stage layout (bytes): Ah 0 (10240) | Al 10240 (10240) | Bh 20480 (4608) | Bl 25088 (4608)
#define STG_B 29696
#define G1_SMEM_B (3*STG_B)     // 89088 bytes
#define QST 72
__global__ __launch_bounds__(256, 2) void k_gemm1tok(const float* __restrict__ x,
                                                  const float* __restrict__ cent,
                                                  const float* __restrict__ ln_g,
                                                  const float* __restrict__ ln_b,
                                                  const float* __restrict__ W1,
                                                  const float* __restrict__ b1,
                                                  const float* __restrict__ W2,
                                                  const float* __restrict__ b2,
                                                  const float* __restrict__ s_logits,
                                                  const float* __restrict__ s_evid,
                                                  const float* __restrict__ s_thr,
                                                  const float* __restrict__ s_slope,
                                                  float* __restrict__ dout){
    extern __shared__ char sm1[];
    __shared__ float qbs[64];
    int tid = threadIdx.x, lane = tid & 31, w = tid >> 5;
    int tok0 = blockIdx.x * 128;
    int b = tok0 >> 12;
    if (tid < 64) qbs[tid] = g_qbias[b*DP + tid];
    int mw = w & 3, nw = w >> 2;
    int m0 = mw*32, n0 = nw*32;

    float acc[2][4][4];
#pragma unroll
    for (int mi = 0; mi < 2; mi++)
#pragma unroll
        for (int nj = 0; nj < 4; nj++)
#pragma unroll
            for (int q = 0; q < 4; q++) acc[mi][nj][q] = 0.f;

    const u16* wph = g_Wph + (size_t)b*DM*DP;
    const u16* wpl = g_Wpl + (size_t)b*DM*DP;
    const u16* xh = g_Xh + (size_t)tok0*DM;
    const u16* xl = g_Xl + (size_t)tok0*DM;
    u32 smbase = sptr(sm1);

    // cp.async granule maps: per thread 4 A granules (2 rows x hi/lo) + 2 B granules
    int arA = tid >> 2, acA = (tid & 3);          // A rows arA, arA+64; granule acA (16B)
    int rB = tid >> 3, cB = tid & 7;              // B: row (0..31), granule (0..7)

    // issue loads of chunk `ck` into stage `st`
    auto issue = [&](int ck, int st){
        int kb = ck*32;
        u32 sbase = smbase + st*STG_B;
#pragma unroll
        for (int p = 0; p < 2; p++){
            int row = arA + p*64;
            size_t asrc = ((size_t)row*DM + kb)*2 + acA*16;
            u32 adst = sbase + row*(A1_ST*2) + acA*16;
            cp16(adst,         (const char*)xh + asrc);
            cp16(adst + 10240, (const char*)xl + asrc);
        }
        size_t bsrc = ((size_t)(kb + rB)*DP)*2 + cB*16;
        u32 bdst = sbase + 20480 + rB*(B1_ST*2) + cB*16;
        cp16(bdst,        (const char*)wph + bsrc);
        cp16(bdst + 4608, (const char*)wpl + bsrc);
    };

    issue(0, 0); CP_COMMIT();
    issue(1, 1); CP_COMMIT();

    for (int it = 0; it < 32; it++){
        CP_WAIT1();
        __syncthreads();
        if (it + 2 < 32) issue(it + 2, (it + 2) % 3);
        CP_COMMIT();

        u32 sbase = smbase + (it % 3)*STG_B;
        u32 a_hi = sbase + ((m0 + (lane & 15))*A1_ST + (lane >> 4)*8)*2;
        u32 a_lo = a_hi + 10240;
        int bk = (lane & 7) + 8*((lane >> 3) & 1);
        u32 b_hi = sbase + 20480 + (bk*B1_ST + n0 + 8*(lane >> 4))*2;
        u32 b_lo = b_hi + 4608;
#pragma unroll
        for (int ks = 0; ks < 2; ks++){
            u32 ah[2][4], al[2][4];
#pragma unroll
            for (int mi = 0; mi < 2; mi++){
                ldm4(ah[mi], a_hi + (mi*16*A1_ST + ks*16)*2);
                ldm4(al[mi], a_lo + (mi*16*A1_ST + ks*16)*2);
            }
            u32 bh[2][4], bl[2][4];
#pragma unroll
            for (int ni = 0; ni < 2; ni++){
                ldm4t(bh[ni], b_hi + (ks*16*B1_ST + ni*16)*2);
                ldm4t(bl[ni], b_lo + (ks*16*B1_ST + ni*16)*2);
            }
#pragma unroll
            for (int mi = 0; mi < 2; mi++)
#pragma unroll
                for (int nj = 0; nj < 4; nj++){
                    u32 h0 = bh[nj>>1][2*(nj&1)], h1 = bh[nj>>1][2*(nj&1)+1];
                    u32 q0 = bl[nj>>1][2*(nj&1)], q1 = bl[nj>>1][2*(nj&1)+1];
                    mma16816(acc[mi][nj], ah[mi], h0, h1);
                    mma16816(acc[mi][nj], ah[mi], q0, q1);
                    mma16816(acc[mi][nj], al[mi], h0, h1);
                }
        }
    }
    __syncthreads();   // pipeline done; re-purpose smem arena

    // ---- smem re-layout (float view) ----
    float* fsm = (float*)sm1;
    float* Qs  = fsm;               // [128][QST] = 9216 floats (qn written in place)
    float* W1s = fsm + 9216;        // 4096
    float* W2s = fsm + 13312;       // 4096
    float* hsA = fsm + 17408;       // 8 warps * 512 = 4096 (ends 21504 <= 22272)

    // stage Q (+qbias) into smem
    {
        int rr = lane >> 2, cc = 2*(lane & 3);
#pragma unroll
        for (int mi = 0; mi < 2; mi++)
#pragma unroll
            for (int nj = 0; nj < 4; nj++){
                int col = n0 + nj*8 + cc;
                float qb0 = qbs[col], qb1 = qbs[col+1];
                int lr = m0 + mi*16 + rr;
                *(float2*)&Qs[lr*QST + col] =
                    make_float2(acc[mi][nj][0] + qb0, acc[mi][nj][1] + qb1);
                *(float2*)&Qs[(lr+8)*QST + col] =
                    make_float2(acc[mi][nj][2] + qb0, acc[mi][nj][3] + qb1);
            }
    }
    for (int i = tid; i < DP*DP; i += 256){ W1s[i] = W1[i]; W2s[i] = W2[i]; }
    __syncthreads();

    // ---- token phase: warp w handles tokens w*16..w*16+15 (2 batches of 8) ----
    int j2 = 2*lane;
    float* hs_w = hsA + w*512;
    float2 lng = *(const float2*)(ln_g + j2);
    float2 lnb = *(const float2*)(ln_b + j2);
    float2 b1v = *(const float2*)(b1 + j2);
    float2 b2v = *(const float2*)(b2 + j2);
    float2 cv[NC], kn[NC];
#pragma unroll
    for (int n = 0; n < NC; n++){
        cv[n] = *(const float2*)(cent + n*DP + j2);
        float ss = wsum(cv[n].x*cv[n].x + cv[n].y*cv[n].y);
        float inv = 1.f / fmaxf(sqrtf(ss), 1e-12f);
        kn[n].x = cv[n].x*inv; kn[n].y = cv[n].y*inv;
    }
    float spl = softplusf(s_logits[0]);
    float spe = softplusf(s_evid[0]);
    float thr = s_thr[0], slope = s_slope[0];
    float taccum = 0.f, caccum = 0.f;

    for (int bb = 0; bb < 2; bb++){
        float hgx[8], hgy[8], nrmv[8];
        // phase A: LN, l2norm, sims, attn, gates; qn written IN PLACE into Qs row
#pragma unroll
        for (int itk = 0; itk < 8; itk++){
            int tl = w*16 + bb*8 + itk;
            int t = tok0 + tl;
            float2 qv = *(const float2*)&Qs[tl*QST + j2];
            float mu = wsum(qv.x + qv.y) * (1.f/64.f);
            float dx = qv.x - mu, dy = qv.y - mu;
            float var = wsum(dx*dx + dy*dy) * (1.f/64.f);
            float rstd = rsqrtf(var + 1e-5f);
            float yx = dx*rstd*lng.x + lnb.x;
            float yy = dy*rstd*lng.y + lnb.y;
            float n2 = wsum(yx*yx + yy*yy);
            float nrm = sqrtf(n2);
            float inv = 1.f / fmaxf(nrm, 1e-12f);
            float qnx = yx*inv, qny = yy*inv;
            *(float2*)&Qs[tl*QST + j2] = make_float2(qnx, qny);
            nrmv[itk] = nrm;

            float sim[NC];
#pragma unroll
            for (int n = 0; n < NC; n++)
                sim[n] = wsum(qnx*kn[n].x + qny*kn[n].y);
            float athr = 0.25f*(sim[0]+sim[1]+sim[2]+sim[3]);
            float ev[NC], mx = -1e30f, S = 0.f;
#pragma unroll
            for (int n = 0; n < NC; n++){
                ev[n] = softplusf((sim[n] - athr)*5.0f) * spe;
                S += ev[n];
                mx = fmaxf(mx, ev[n]);
            }
            S += (float)NC;
            float ustd = (float)NC / S;
            float uresp = 1.f / (1.f + log1pf(mx * (float)NC));
            float Temp = 0.1f + 0.9f / (1.f + expf(-slope*(uresp - thr)));
            float lg[NC], lm = -1e30f;
#pragma unroll
            for (int n = 0; n < NC; n++){ lg[n] = sim[n]*spl/Temp; lm = fmaxf(lm, lg[n]); }
            float es = 0.f, e[NC];
#pragma unroll
            for (int n = 0; n < NC; n++){ e[n] = expf(lg[n]-lm); es += e[n]; }
            float attn[NC];
#pragma unroll
            for (int n = 0; n < NC; n++) attn[n] = e[n]/es;

            float hx = 0.f, hy = 0.f;
#pragma unroll
            for (int n = 0; n < NC; n++){
                hx += attn[n]*cv[n].x;
                hy += attn[n]*cv[n].y;
            }
            hgx[itk] = hx; hgy[itk] = hy;

            if (lane == 0){
                taccum += Temp;
                dout[USTD_OFF + (size_t)t] = ustd;
                dout[ATTN_OFF + (size_t)t*4 + 0] = attn[0];
                dout[ATTN_OFF + (size_t)t*4 + 1] = attn[1];
                dout[ATTN_OFF + (size_t)t*4 + 2] = attn[2];
                dout[ATTN_OFF + (size_t)t*4 + 3] = attn[3];
                float ig = (1.f - uresp);
                g_gate[t] = ig*ig;
            }
        }
        __syncwarp();

        // B1: h = tanh(qn @ W1 + b1)  (qn read from Qs; h into hs_w)
        float hx[8], hy[8];
#pragma unroll
        for (int itk = 0; itk < 8; itk++){ hx[itk] = b1v.x; hy[itk] = b1v.y; }
#pragma unroll 4
        for (int d = 0; d < DP; d++){
            float2 wv = *(const float2*)&W1s[d*DP + j2];
#pragma unroll
            for (int itk = 0; itk < 8; itk++){
                float qd = Qs[(w*16 + bb*8 + itk)*QST + d];
                hx[itk] += qd*wv.x; hy[itk] += qd*wv.y;
            }
        }
#pragma unroll
        for (int itk = 0; itk < 8; itk++){
            hx[itk] = tanhf(hx[itk]); hy[itk] = tanhf(hy[itk]);
            *(float2*)&hs_w[itk*64 + j2] = make_float2(hx[itk], hy[itk]);
        }
        __syncwarp();

        // B2: o = h @ W2 + b2
        float ox[8], oy[8];
#pragma unroll
        for (int itk = 0; itk < 8; itk++){ ox[itk] = b2v.x; oy[itk] = b2v.y; }
#pragma unroll 4
        for (int d = 0; d < DP; d++){
            float2 wv = *(const float2*)&W2s[d*DP + j2];
#pragma unroll
            for (int itk = 0; itk < 8; itk++){
                float hd = hs_w[itk*64 + d];
                ox[itk] += hd*wv.x; oy[itk] += hd*wv.y;
            }
        }

        // phase C: offsets out, cos accum (qn re-read from Qs)
#pragma unroll
        for (int itk = 0; itk < 8; itk++){
            int tl = w*16 + bb*8 + itk;
            int t = tok0 + tl;
            *(u32*)(g_Ob + (size_t)t*DP + j2) = bf2(ox[itk], oy[itk]);
            float2 qn = *(const float2*)&Qs[tl*QST + j2];
            float hrx = hgx[itk] + ox[itk], hry = hgy[itk] + oy[itk];
            float dotqn = wsum(hrx*qn.x + hry*qn.y);
            float hn2 = wsum(hrx*hrx + hry*hry);
            float nrm = nrmv[itk];
            float cosv = (nrm*dotqn) / (fmaxf(sqrtf(hn2), 1e-8f) * fmaxf(nrm, 1e-8f));
            if (lane == 0) caccum += cosv;
        }
        __syncwarp();
    }
    if (lane == 0){
        atomicAdd(&g_temp_sum, taccum);
        atomicAdd(&g_cos_sum, caccum);
    }
}

// ---------------- GEMM2: out = gate*(offset@Wo + attn@CWo + bo) + x ----------------
#define A2_ST 72
#define B2_ST 136
#define G2_SMEM_B ((9216 + 8704)*2)   // 35840 bytes
__global__ __launch_bounds__(512) void k_gemm2(const float* __restrict__ x,
                                               const float* __restrict__ bo,
                                               const float* __restrict__ dout_ro,
                                               float* __restrict__ out){
    extern __shared__ u16 sm2[];
    u16* Ah = sm2;
    u16* Bh = sm2 + 9216;
    __shared__ float gsm[128], bos[128];
    __shared__ float attns[128][4];
    __shared__ float cwos[4][128];
    int tid = threadIdx.x, lane = tid & 31, w = tid >> 5;
    int tok0 = blockIdx.y * 128;
    int db = blockIdx.x * 128;

#pragma unroll
    for (int p = 0; p < 2; p++){
        int i = tid + p*512;
        int r = i >> 3, c = (i & 7)*8;
        *(uint4*)(Ah + r*A2_ST + c) = *(const uint4*)(g_Ob + (size_t)(tok0 + r)*DP + c);
    }
#pragma unroll
    for (int p = 0; p < 2; p++){
        int i = tid + p*512;
        int kr = i >> 4, c = (i & 15)*8;
        *(uint4*)(Bh + kr*B2_ST + c) = *(const uint4*)(g_Woh + (size_t)kr*DM + db + c);
    }
    if (tid < 128){ gsm[tid] = g_gate[tok0 + tid]; bos[tid] = bo[db + tid]; }
    attns[tid >> 2][tid & 3] = dout_ro[ATTN_OFF + (size_t)(tok0 + (tid >> 2))*4 + (tid & 3)];
    cwos[tid >> 7][tid & 127] = g_CWo[(size_t)(tid >> 7)*DM + db + (tid & 127)];
    __syncthreads();

    int mw = w & 3, nw = w >> 2;
    int m0 = mw*32, n0 = nw*32;
    float acc[2][4][4];
#pragma unroll
    for (int mi = 0; mi < 2; mi++)
#pragma unroll
        for (int nj = 0; nj < 4; nj++)
#pragma unroll
            for (int q = 0; q < 4; q++) acc[mi][nj][q] = 0.f;

    u32 a_base = sptr(Ah) + ((m0 + (lane & 15))*A2_ST + (lane >> 4)*8)*2;
    int bk = (lane & 7) + 8*((lane >> 3) & 1);
    u32 b_base = sptr(Bh) + (bk*B2_ST + n0 + 8*(lane >> 4))*2;

#pragma unroll
    for (int ks = 0; ks < 4; ks++){
        u32 ah[2][4];
#pragma unroll
        for (int mi = 0; mi < 2; mi++)
            ldm4(ah[mi], a_base + (mi*16*A2_ST + ks*16)*2);
        u32 bh[2][4];
#pragma unroll
        for (int ni = 0; ni < 2; ni++)
            ldm4t(bh[ni], b_base + (ks*16*B2_ST + ni*16)*2);
#pragma unroll
        for (int mi = 0; mi < 2; mi++)
#pragma unroll
            for (int nj = 0; nj < 4; nj++)
                mma16816(acc[mi][nj], ah[mi], bh[nj>>1][2*(nj&1)], bh[nj>>1][2*(nj&1)+1]);
    }

    int rr = lane >> 2, cc = 2*(lane & 3);
#pragma unroll
    for (int mi = 0; mi < 2; mi++)
#pragma unroll
        for (int nj = 0; nj < 4; nj++){
            int col = n0 + nj*8 + cc;
            float bo0 = bos[col], bo1 = bos[col+1];
            float cw00 = cwos[0][col], cw01 = cwos[0][col+1];
            float cw10 = cwos[1][col], cw11 = cwos[1][col+1];
            float cw20 = cwos[2][col], cw21 = cwos[2][col+1];
            float cw30 = cwos[3][col], cw31 = cwos[3][col+1];
#pragma unroll
            for (int half = 0; half < 2; half++){
                int lrow = m0 + mi*16 + rr + half*8;
                float a0 = attns[lrow][0], a1 = attns[lrow][1];
                float a2 = attns[lrow][2], a3 = attns[lrow][3];
                float geo0 = a0*cw00 + a1*cw10 + a2*cw20 + a3*cw30;
                float geo1 = a0*cw01 + a1*cw11 + a2*cw21 + a3*cw31;
                float g = gsm[lrow];
                size_t off = (size_t)(tok0 + lrow)*DM + db + col;
                float2 xv = *(const float2*)(x + off);
                float2 o = make_float2(
                    g*(acc[mi][nj][2*half+0] + geo0 + bo0) + xv.x,
                    g*(acc[mi][nj][2*half+1] + geo1 + bo1) + xv.y);
                *(float2*)(out + off) = o;
            }
        }
}

// ---------------- scalars: ortho, temp mean, latent, geo ----------------
__global__ void k_final(const float* __restrict__ cent, float* __restrict__ dout){
    __shared__ float Kn[NC][DP];
    __shared__ float norms[NC];
    __shared__ float part[16];
    int tid = threadIdx.x;   // 64 threads
    if (tid < NC){
        float ss = 0.f;
        for (int d = 0; d < DP; d++){ float c = cent[tid*DP + d]; ss += c*c; }
        norms[tid] = fmaxf(sqrtf(ss), 1e-12f);
    }
    __syncthreads();
    if (tid < DP){
        for (int n = 0; n < NC; n++) Kn[n][tid] = cent[n*DP + tid] / norms[n];
    }
    __syncthreads();
    if (tid < 16){
        int i = tid >> 2, j = tid & 3;
        float dot = 0.f;
        for (int d = 0; d < DP; d++) dot += Kn[i][d]*Kn[j][d];
        float e2 = dot - (i == j ? 1.f : 0.f);
        part[tid] = e2*e2;
    }
    __syncthreads();
    if (tid == 0){
        float s = 0.f;
        for (int p = 0; p < 16; p++) s += part[p];
        dout[ORTHO_OFF] = s / 16.f;
        dout[TEMP_OFF] = g_temp_sum / (float)NTOK;
        dout[GEO_OFF] = 0.f;
        dout[LATENT_OFF] = 1.f - g_cos_sum / (float)NTOK;
    }
}

extern "C" void kernel_launch(void* const* d_in, const int* in_sizes, int n_in,
                              void* d_out, int out_size){
    const float* x    = (const float*)d_in[0];
    const float* Wp   = (const float*)d_in[1];
    const float* bp   = (const float*)d_in[2];
    const float* ln_g = (const float*)d_in[3];
    const float* ln_b = (const float*)d_in[4];
    const float* cent = (const float*)d_in[5];
    const float* Wo   = (const float*)d_in[6];
    const float* bo   = (const float*)d_in[7];
    const float* W1   = (const float*)d_in[8];
    const float* b1   = (const float*)d_in[9];
    const float* W2   = (const float*)d_in[10];
    const float* b2   = (const float*)d_in[11];
    const float* sl   = (const float*)d_in[12];
    const float* se   = (const float*)d_in[13];
    const float* tt   = (const float*)d_in[14];
    const float* ts   = (const float*)d_in[15];
    float* out = (float*)d_out;

    static int smem_set = 0;
    if (!smem_set){
        cudaFuncSetAttribute(k_gemm1tok, cudaFuncAttributeMaxDynamicSharedMemorySize, G1_SMEM_B);
        cudaFuncSetAttribute(k_gemm2, cudaFuncAttributeMaxDynamicSharedMemorySize, G2_SMEM_B);
        smem_set = 1;
    }

    // my launch index 3 = ncu's profiled slot (2 harness launches precede)
    k_stats<<<dim3(BB, NCHUNK), 256>>>(x);                   // 0
    k_finstats<<<64, 256>>>();                               // 1
    k_prewc<<<1040, 256>>>(Wp, bp);                          // 2
    k_gemm1tok<<<NTOK/128, 256, G1_SMEM_B>>>(x, cent, ln_g, ln_b, W1, b1, W2, b2,
                                             sl, se, tt, ts, out);  // 3 <-- profiled
    k_prewo<<<64, 256>>>(Wo);                                // 4
    k_precw<<<4, 256>>>(cent, Wo);                           // 5
    k_gemm2<<<dim3(DM/128, NTOK/128), 512, G2_SMEM_B>>>(x, bo, out, out);  // 6
    k_final<<<1, 64>>>(cent, out);                           // 7
}

// round 17
// speedup vs baseline: 1.1160x; 1.1160x over previous
#include <cuda_runtime.h>
#include <math.h>

typedef unsigned int u32;
typedef unsigned short u16;
typedef unsigned long long u64;

#define BB 16
#define TT 4096
#define DM 1024
#define DP 64
#define NC 4
#define NTOK (BB*TT)            // 65536

// output layout (flat fp32, tuple order)
#define OUT_OFF    0ull
#define USTD_OFF   67108864ull
#define TEMP_OFF   67174400ull
#define ATTN_OFF   67174401ull
#define ORTHO_OFF  67436545ull
#define GEO_OFF    67436546ull
#define LATENT_OFF 67436547ull

#define NCHUNK 32
#define SCHUNK (TT/NCHUNK)      // 128

// scratch
__device__ float g_ps[BB*NCHUNK*DM];          // partial sums
__device__ float g_pq[BB*NCHUNK*DM];          // partial sumsq
__device__ float g_mean[BB*DM];
__device__ float g_rs[BB*DM];
__device__ u16   g_Wph[(size_t)BB*DM*DP];     // bf16 hi of rs*Wp
__device__ u16   g_Wpl[(size_t)BB*DM*DP];     // bf16 lo
__device__ u16   g_Woh[DP*DM];                // bf16 (single plane)
__device__ float g_CWo[NC*DM];                // centroids @ Wo  [4][1024]
__device__ float g_qbias[BB*DP];
__device__ u16   g_Ob[(size_t)NTOK*DP];       // offset, bf16 single plane
__device__ float g_gate[NTOK];
__device__ float g_temp_sum;
__device__ float g_cos_sum;

__device__ __forceinline__ float wsum(float v){
#pragma unroll
    for (int m = 16; m; m >>= 1) v += __shfl_xor_sync(0xffffffffu, v, m);
    return v;
}
__device__ __forceinline__ float softplusf(float v){
    return (v > 20.f) ? v : log1pf(expf(v));
}
// pack: low half = bf16(x), high half = bf16(y)
__device__ __forceinline__ u32 bf2(float x, float y){
    u32 r; asm("cvt.rn.bf16x2.f32 %0, %1, %2;" : "=r"(r) : "f"(y), "f"(x)); return r;
}
__device__ __forceinline__ void split2(float x, float y, u32 &h, u32 &l){
    h = bf2(x, y);
    float xh = __uint_as_float(h << 16);
    float yh = __uint_as_float(h & 0xFFFF0000u);
    l = bf2(x - xh, y - yh);
}
__device__ __forceinline__ u32 sptr(const void* p){
    return (u32)__cvta_generic_to_shared(p);
}
__device__ __forceinline__ void ldm4(u32* r, u32 addr){
    asm volatile("ldmatrix.sync.aligned.m8n8.x4.shared.b16 {%0,%1,%2,%3}, [%4];"
        : "=r"(r[0]),"=r"(r[1]),"=r"(r[2]),"=r"(r[3]) : "r"(addr));
}
__device__ __forceinline__ void ldm4t(u32* r, u32 addr){
    asm volatile("ldmatrix.sync.aligned.m8n8.x4.trans.shared.b16 {%0,%1,%2,%3}, [%4];"
        : "=r"(r[0]),"=r"(r[1]),"=r"(r[2]),"=r"(r[3]) : "r"(addr));
}
__device__ __forceinline__ void mma16816(float* c, const u32* a, u32 b0, u32 b1){
    asm volatile("mma.sync.aligned.m16n8k16.row.col.f32.bf16.bf16.f32 "
        "{%0,%1,%2,%3},{%4,%5,%6,%7},{%8,%9},{%0,%1,%2,%3};"
        : "+f"(c[0]),"+f"(c[1]),"+f"(c[2]),"+f"(c[3])
        : "r"(a[0]),"r"(a[1]),"r"(a[2]),"r"(a[3]),"r"(b0),"r"(b1));
}

// ---------------- stats over T: atomic-free partial sums ----------------
__global__ __launch_bounds__(256) void k_stats(const float* __restrict__ x){
    int b = blockIdx.x;
    int chunk = blockIdx.y;
    int c4 = threadIdx.x*4;
    const float* p = x + ((size_t)b*TT + (size_t)chunk*SCHUNK)*DM + c4;
    float4 s = make_float4(0,0,0,0), s2 = make_float4(0,0,0,0);
#pragma unroll 4
    for (int t = 0; t < SCHUNK; t++){
        float4 v = *(const float4*)(p + (size_t)t*DM);
        s.x += v.x; s.y += v.y; s.z += v.z; s.w += v.w;
        s2.x += v.x*v.x; s2.y += v.y*v.y; s2.z += v.z*v.z; s2.w += v.w*v.w;
    }
    size_t o = ((size_t)b*NCHUNK + chunk)*DM + c4;
    *(float4*)(g_ps + o) = s;
    *(float4*)(g_pq + o) = s2;
}

__global__ void k_finstats(){
    int i = blockIdx.x*256 + threadIdx.x;
    if (i < BB*DM){
        int b = i >> 10, d = i & (DM-1);
        float s = 0.f, s2 = 0.f;
        const float* ps = g_ps + (size_t)b*NCHUNK*DM + d;
        const float* pq = g_pq + (size_t)b*NCHUNK*DM + d;
#pragma unroll 8
        for (int c = 0; c < NCHUNK; c++){
            s += ps[(size_t)c*DM];
            s2 += pq[(size_t)c*DM];
        }
        float mean = s / (float)TT;
        float var = (s2 - s*mean) / (float)(TT - 1);
        var = fmaxf(var, 0.f);
        float sd = sqrtf(var) + 1e-5f;
        g_mean[i] = mean;
        g_rs[i] = 1.f / sd;
    }
    if (i == 0){ g_temp_sum = 0.f; g_cos_sum = 0.f; }
}

// ---------------- merged preprocessing: Wp split | qbias | Wo bf16 | CWo ----------------
__global__ __launch_bounds__(256) void k_prewc(const float* __restrict__ Wp,
                                               const float* __restrict__ bp,
                                               const float* __restrict__ Wo,
                                               const float* __restrict__ cent){
    if (blockIdx.x < 1024){
        int i = blockIdx.x*256 + threadIdx.x;      // BB*DM*16 float4s
        int j4 = i & 15;
        int rem = i >> 4;
        int d = rem & (DM-1);
        float r = g_rs[rem];
        float4 w = *(const float4*)(Wp + (size_t)d*DP + j4*4);
        float4 o; o.x = w.x*r; o.y = w.y*r; o.z = w.z*r; o.w = w.w*r;
        u32 h0,l0,h1,l1;
        split2(o.x, o.y, h0, l0);
        split2(o.z, o.w, h1, l1);
        *(uint2*)(g_Wph + (size_t)rem*DP + j4*4) = make_uint2(h0, h1);
        *(uint2*)(g_Wpl + (size_t)rem*DP + j4*4) = make_uint2(l0, l1);
    } else if (blockIdx.x < 1040){
        __shared__ float red[256];
        int b = blockIdx.x - 1024;
        int t = threadIdx.x;
        int j = t & 63, part = t >> 6;
        float s = 0.f;
        const float* mn = g_mean + b*DM;
        const float* rs = g_rs + b*DM;
#pragma unroll 8
        for (int d = part*256; d < part*256 + 256; d++)
            s += mn[d] * rs[d] * Wp[(size_t)d*DP + j];
        red[t] = s;
        __syncthreads();
        if (t < 64)
            g_qbias[b*DP + j] = bp[j] - (red[j] + red[j+64] + red[j+128] + red[j+192]);
    } else if (blockIdx.x < 1104){
        int i = (blockIdx.x - 1040)*256 + threadIdx.x;   // 16384 float4
        float4 w = *(const float4*)(Wo + (size_t)i*4);
        *(uint2*)(g_Woh + (size_t)i*4) = make_uint2(bf2(w.x, w.y), bf2(w.z, w.w));
    } else {
        int j = (blockIdx.x - 1104)*256 + threadIdx.x;   // 1024 cols
        float s0=0.f, s1=0.f, s2=0.f, s3=0.f;
#pragma unroll 8
        for (int d = 0; d < DP; d++){
            float w = Wo[(size_t)d*DM + j];
            s0 += cent[0*DP+d]*w;
            s1 += cent[1*DP+d]*w;
            s2 += cent[2*DP+d]*w;
            s3 += cent[3*DP+d]*w;
        }
        g_CWo[0*DM+j]=s0; g_CWo[1*DM+j]=s1; g_CWo[2*DM+j]=s2; g_CWo[3*DM+j]=s3;
    }
}

// ---------------- FUSED GEMM1 + token math ----------------
// CTA: 128 tok x 64 n. K chunks of 64, double-buffered, 1 sync/iter (16 iters).
// 8 warps 4m x 2n. Coalesced A loads, register prefetch. Token phase in-CTA.
#define A1_ST 72
#define B1_ST 72
// u16 per buffer: Ah 9216 | Al 9216 | Bh 4608 | Bl 4608 = 27648
#define G1BUF 27648
#define G1_SMEM_B (2*G1BUF*2)   // 110592 bytes
#define QST 72
__global__ __launch_bounds__(256, 2) void k_gemm1tok(const float* __restrict__ x,
                                                  const float* __restrict__ cent,
                                                  const float* __restrict__ ln_g,
                                                  const float* __restrict__ ln_b,
                                                  const float* __restrict__ W1,
                                                  const float* __restrict__ b1,
                                                  const float* __restrict__ W2,
                                                  const float* __restrict__ b2,
                                                  const float* __restrict__ s_logits,
                                                  const float* __restrict__ s_evid,
                                                  const float* __restrict__ s_thr,
                                                  const float* __restrict__ s_slope,
                                                  float* __restrict__ dout){
    extern __shared__ u16 sm1[];
    __shared__ float qbs[64];
    int tid = threadIdx.x, lane = tid & 31, w = tid >> 5;
    int tok0 = blockIdx.x * 128;
    int b = tok0 >> 12;
    if (tid < 64) qbs[tid] = g_qbias[b*DP + tid];
    int mw = w & 3, nw = w >> 2;
    int m0 = mw*32, n0 = nw*32;

    float acc[2][4][4];
#pragma unroll
    for (int mi = 0; mi < 2; mi++)
#pragma unroll
        for (int nj = 0; nj < 4; nj++)
#pragma unroll
            for (int q = 0; q < 4; q++) acc[mi][nj][q] = 0.f;

    const u16* wph = g_Wph + (size_t)b*DM*DP;
    const u16* wpl = g_Wpl + (size_t)b*DM*DP;
    // A: coalesced — rows ar, ar+32, ar+64, ar+96; per row 2 float4 (cols ac4, ac4+32)
    int ar = tid >> 3, ac4 = (tid & 7)*4;
    const float* xbase = x + (size_t)(tok0 + ar)*DM + ac4;
    // B: row rb (0..63), cols cb*16..+15 (2 uint4 per plane)
    int rb = tid >> 2, cb = (tid & 3)*16;

    float4 areg[4][2];
    uint4 bh0, bh1, bl0, bl1;
#pragma unroll
    for (int p = 0; p < 4; p++)
#pragma unroll
        for (int q = 0; q < 2; q++)
            areg[p][q] = *(const float4*)(xbase + (size_t)p*32*DM + q*32);
    bh0 = *(const uint4*)(wph + (size_t)rb*DP + cb);
    bh1 = *(const uint4*)(wph + (size_t)rb*DP + cb + 8);
    bl0 = *(const uint4*)(wpl + (size_t)rb*DP + cb);
    bl1 = *(const uint4*)(wpl + (size_t)rb*DP + cb + 8);

    for (int it = 0; it < DM/64; it++){
        u16* base = sm1 + (it & 1)*G1BUF;
        u16* Ah = base;
        u16* Al = base + 9216;
        u16* Bh = base + 18432;
        u16* Bl = base + 23040;
        {
#pragma unroll
            for (int p = 0; p < 4; p++){
                int off = (ar + p*32)*A1_ST + ac4;
#pragma unroll
                for (int q = 0; q < 2; q++){
                    float4 v = areg[p][q];
                    u32 h0,l0,h1,l1;
                    split2(v.x, v.y, h0, l0);
                    split2(v.z, v.w, h1, l1);
                    *(uint2*)(Ah + off + q*32) = make_uint2(h0, h1);
                    *(uint2*)(Al + off + q*32) = make_uint2(l0, l1);
                }
            }
        }
        {
            int off = rb*B1_ST + cb;
            *(uint4*)(Bh + off)     = bh0;
            *(uint4*)(Bh + off + 8) = bh1;
            *(uint4*)(Bl + off)     = bl0;
            *(uint4*)(Bl + off + 8) = bl1;
        }
        if (it < DM/64 - 1){
            int kb = (it + 1)*64;
#pragma unroll
            for (int p = 0; p < 4; p++)
#pragma unroll
                for (int q = 0; q < 2; q++)
                    areg[p][q] = *(const float4*)(xbase + (size_t)p*32*DM + kb + q*32);
            bh0 = *(const uint4*)(wph + (size_t)(kb + rb)*DP + cb);
            bh1 = *(const uint4*)(wph + (size_t)(kb + rb)*DP + cb + 8);
            bl0 = *(const uint4*)(wpl + (size_t)(kb + rb)*DP + cb);
            bl1 = *(const uint4*)(wpl + (size_t)(kb + rb)*DP + cb + 8);
        }
        __syncthreads();

        u32 a_hi = sptr(Ah) + ((m0 + (lane & 15))*A1_ST + (lane >> 4)*8)*2;
        u32 a_lo = a_hi + 9216*2;
        int bk = (lane & 7) + 8*((lane >> 3) & 1);
        u32 b_hi = sptr(Bh) + (bk*B1_ST + n0 + 8*(lane >> 4))*2;
        u32 b_lo = b_hi + 4608*2;
#pragma unroll
        for (int ks = 0; ks < 4; ks++){
            u32 ah[2][4], al[2][4];
#pragma unroll
            for (int mi = 0; mi < 2; mi++){
                ldm4(ah[mi], a_hi + (mi*16*A1_ST + ks*16)*2);
                ldm4(al[mi], a_lo + (mi*16*A1_ST + ks*16)*2);
            }
            u32 bh[2][4], bl[2][4];
#pragma unroll
            for (int ni = 0; ni < 2; ni++){
                ldm4t(bh[ni], b_hi + (ks*16*B1_ST + ni*16)*2);
                ldm4t(bl[ni], b_lo + (ks*16*B1_ST + ni*16)*2);
            }
#pragma unroll
            for (int mi = 0; mi < 2; mi++)
#pragma unroll
                for (int nj = 0; nj < 4; nj++){
                    u32 h0 = bh[nj>>1][2*(nj&1)], h1 = bh[nj>>1][2*(nj&1)+1];
                    u32 q0 = bl[nj>>1][2*(nj&1)], q1 = bl[nj>>1][2*(nj&1)+1];
                    mma16816(acc[mi][nj], ah[mi], h0, h1);
                    mma16816(acc[mi][nj], ah[mi], q0, q1);
                    mma16816(acc[mi][nj], al[mi], h0, h1);
                }
        }
        // buffer it&1 rewritten at it+2, after sync(it+1) which all warps pass only
        // once compute(it) is done — WAR safe with a single barrier per iteration.
    }
    __syncthreads();   // K buffers dead; re-purpose smem arena

    // ---- smem re-layout (float view) ----
    float* fsm = (float*)sm1;
    float* Qs  = fsm;               // [128][QST] = 9216 floats
    float* W1s = fsm + 9216;        // 4096
    float* W2s = fsm + 13312;       // 4096
    float* qnA = fsm + 17408;       // 8 warps * 512
    float* hsA = fsm + 21504;       // 8 warps * 512  (total 25600 f = 102400 B)

    // stage Q (+qbias) into smem
    {
        int rr = lane >> 2, cc = 2*(lane & 3);
#pragma unroll
        for (int mi = 0; mi < 2; mi++)
#pragma unroll
            for (int nj = 0; nj < 4; nj++){
                int col = n0 + nj*8 + cc;
                float qb0 = qbs[col], qb1 = qbs[col+1];
                int lr = m0 + mi*16 + rr;
                *(float2*)&Qs[lr*QST + col] =
                    make_float2(acc[mi][nj][0] + qb0, acc[mi][nj][1] + qb1);
                *(float2*)&Qs[(lr+8)*QST + col] =
                    make_float2(acc[mi][nj][2] + qb0, acc[mi][nj][3] + qb1);
            }
    }
    for (int i = tid; i < DP*DP; i += 256){ W1s[i] = W1[i]; W2s[i] = W2[i]; }
    __syncthreads();

    // ---- token phase: warp w handles tokens w*16..w*16+15 (2 batches of 8) ----
    int j2 = 2*lane;
    float* qn_w = qnA + w*512;
    float* hs_w = hsA + w*512;
    float2 lng = *(const float2*)(ln_g + j2);
    float2 lnb = *(const float2*)(ln_b + j2);
    float2 b1v = *(const float2*)(b1 + j2);
    float2 b2v = *(const float2*)(b2 + j2);
    float2 cv[NC], kn[NC];
#pragma unroll
    for (int n = 0; n < NC; n++){
        cv[n] = *(const float2*)(cent + n*DP + j2);
        float ss = wsum(cv[n].x*cv[n].x + cv[n].y*cv[n].y);
        float inv = 1.f / fmaxf(sqrtf(ss), 1e-12f);
        kn[n].x = cv[n].x*inv; kn[n].y = cv[n].y*inv;
    }
    float spl = softplusf(s_logits[0]);
    float spe = softplusf(s_evid[0]);
    float thr = s_thr[0], slope = s_slope[0];
    float taccum = 0.f, caccum = 0.f;

    for (int bb = 0; bb < 2; bb++){
        float yxv[8], yyv[8], hgx[8], hgy[8], nrmv[8];
#pragma unroll
        for (int itk = 0; itk < 8; itk++){
            int tl = w*16 + bb*8 + itk;
            int t = tok0 + tl;
            float2 qv = *(const float2*)&Qs[tl*QST + j2];
            float mu = wsum(qv.x + qv.y) * (1.f/64.f);
            float dx = qv.x - mu, dy = qv.y - mu;
            float var = wsum(dx*dx + dy*dy) * (1.f/64.f);
            float rstd = rsqrtf(var + 1e-5f);
            float yx = dx*rstd*lng.x + lnb.x;
            float yy = dy*rstd*lng.y + lnb.y;
            float n2 = wsum(yx*yx + yy*yy);
            float nrm = sqrtf(n2);
            float inv = 1.f / fmaxf(nrm, 1e-12f);
            float qnx = yx*inv, qny = yy*inv;
            *(float2*)&qn_w[itk*64 + j2] = make_float2(qnx, qny);
            yxv[itk] = yx; yyv[itk] = yy; nrmv[itk] = nrm;

            float sim[NC];
#pragma unroll
            for (int n = 0; n < NC; n++)
                sim[n] = wsum(qnx*kn[n].x + qny*kn[n].y);
            float athr = 0.25f*(sim[0]+sim[1]+sim[2]+sim[3]);
            float ev[NC], mx = -1e30f, S = 0.f;
#pragma unroll
            for (int n = 0; n < NC; n++){
                ev[n] = softplusf((sim[n] - athr)*5.0f) * spe;
                S += ev[n];
                mx = fmaxf(mx, ev[n]);
            }
            S += (float)NC;
            float ustd = (float)NC / S;
            float uresp = 1.f / (1.f + log1pf(mx * (float)NC));
            float Temp = 0.1f + 0.9f / (1.f + expf(-slope*(uresp - thr)));
            float lg[NC], lm = -1e30f;
#pragma unroll
            for (int n = 0; n < NC; n++){ lg[n] = sim[n]*spl/Temp; lm = fmaxf(lm, lg[n]); }
            float es = 0.f, e[NC];
#pragma unroll
            for (int n = 0; n < NC; n++){ e[n] = expf(lg[n]-lm); es += e[n]; }
            float attn[NC];
#pragma unroll
            for (int n = 0; n < NC; n++) attn[n] = e[n]/es;

            float hx = 0.f, hy = 0.f;
#pragma unroll
            for (int n = 0; n < NC; n++){
                hx += attn[n]*cv[n].x;
                hy += attn[n]*cv[n].y;
            }
            hgx[itk] = hx; hgy[itk] = hy;

            if (lane == 0){
                taccum += Temp;
                dout[USTD_OFF + (size_t)t] = ustd;
                dout[ATTN_OFF + (size_t)t*4 + 0] = attn[0];
                dout[ATTN_OFF + (size_t)t*4 + 1] = attn[1];
                dout[ATTN_OFF + (size_t)t*4 + 2] = attn[2];
                dout[ATTN_OFF + (size_t)t*4 + 3] = attn[3];
                float ig = (1.f - uresp);
                g_gate[t] = ig*ig;
            }
        }
        __syncwarp();

        float hx[8], hy[8];
#pragma unroll
        for (int itk = 0; itk < 8; itk++){ hx[itk] = b1v.x; hy[itk] = b1v.y; }
#pragma unroll 4
        for (int d = 0; d < DP; d++){
            float2 wv = *(const float2*)&W1s[d*DP + j2];
#pragma unroll
            for (int itk = 0; itk < 8; itk++){
                float qd = qn_w[itk*64 + d];
                hx[itk] += qd*wv.x; hy[itk] += qd*wv.y;
            }
        }
#pragma unroll
        for (int itk = 0; itk < 8; itk++){
            hx[itk] = tanhf(hx[itk]); hy[itk] = tanhf(hy[itk]);
            *(float2*)&hs_w[itk*64 + j2] = make_float2(hx[itk], hy[itk]);
        }
        __syncwarp();

        float ox[8], oy[8];
#pragma unroll
        for (int itk = 0; itk < 8; itk++){ ox[itk] = b2v.x; oy[itk] = b2v.y; }
#pragma unroll 4
        for (int d = 0; d < DP; d++){
            float2 wv = *(const float2*)&W2s[d*DP + j2];
#pragma unroll
            for (int itk = 0; itk < 8; itk++){
                float hd = hs_w[itk*64 + d];
                ox[itk] += hd*wv.x; oy[itk] += hd*wv.y;
            }
        }

#pragma unroll
        for (int itk = 0; itk < 8; itk++){
            int t = tok0 + w*16 + bb*8 + itk;
            *(u32*)(g_Ob + (size_t)t*DP + j2) = bf2(ox[itk], oy[itk]);
            float hrx = hgx[itk] + ox[itk], hry = hgy[itk] + oy[itk];
            float dot = wsum(hrx*yxv[itk] + hry*yyv[itk]);
            float hn2 = wsum(hrx*hrx + hry*hry);
            float cosv = dot / (fmaxf(sqrtf(hn2), 1e-8f) * fmaxf(nrmv[itk], 1e-8f));
            if (lane == 0) caccum += cosv;
        }
        __syncwarp();
    }
    if (lane == 0){
        atomicAdd(&g_temp_sum, taccum);
        atomicAdd(&g_cos_sum, caccum);
    }
}

// ---------------- GEMM2: out = gate*(offset@Wo + attn@CWo + bo) + x ----------------
#define A2_ST 72
#define B2_ST 136
#define G2_SMEM_B ((9216 + 8704)*2)   // 35840 bytes
__global__ __launch_bounds__(512) void k_gemm2(const float* __restrict__ x,
                                               const float* __restrict__ bo,
                                               const float* __restrict__ dout_ro,
                                               float* __restrict__ out){
    extern __shared__ u16 sm2[];
    u16* Ah = sm2;
    u16* Bh = sm2 + 9216;
    __shared__ float gsm[128], bos[128];
    __shared__ float attns[128][4];
    __shared__ float cwos[4][128];
    int tid = threadIdx.x, lane = tid & 31, w = tid >> 5;
    int tok0 = blockIdx.y * 128;
    int db = blockIdx.x * 128;

#pragma unroll
    for (int p = 0; p < 2; p++){
        int i = tid + p*512;
        int r = i >> 3, c = (i & 7)*8;
        *(uint4*)(Ah + r*A2_ST + c) = *(const uint4*)(g_Ob + (size_t)(tok0 + r)*DP + c);
    }
#pragma unroll
    for (int p = 0; p < 2; p++){
        int i = tid + p*512;
        int kr = i >> 4, c = (i & 15)*8;
        *(uint4*)(Bh + kr*B2_ST + c) = *(const uint4*)(g_Woh + (size_t)kr*DM + db + c);
    }
    if (tid < 128){ gsm[tid] = g_gate[tok0 + tid]; bos[tid] = bo[db + tid]; }
    attns[tid >> 2][tid & 3] = dout_ro[ATTN_OFF + (size_t)(tok0 + (tid >> 2))*4 + (tid & 3)];
    cwos[tid >> 7][tid & 127] = g_CWo[(size_t)(tid >> 7)*DM + db + (tid & 127)];
    __syncthreads();

    int mw = w & 3, nw = w >> 2;
    int m0 = mw*32, n0 = nw*32;
    float acc[2][4][4];
#pragma unroll
    for (int mi = 0; mi < 2; mi++)
#pragma unroll
        for (int nj = 0; nj < 4; nj++)
#pragma unroll
            for (int q = 0; q < 4; q++) acc[mi][nj][q] = 0.f;

    u32 a_base = sptr(Ah) + ((m0 + (lane & 15))*A2_ST + (lane >> 4)*8)*2;
    int bk = (lane & 7) + 8*((lane >> 3) & 1);
    u32 b_base = sptr(Bh) + (bk*B2_ST + n0 + 8*(lane >> 4))*2;

#pragma unroll
    for (int ks = 0; ks < 4; ks++){
        u32 ah[2][4];
#pragma unroll
        for (int mi = 0; mi < 2; mi++)
            ldm4(ah[mi], a_base + (mi*16*A2_ST + ks*16)*2);
        u32 bh[2][4];
#pragma unroll
        for (int ni = 0; ni < 2; ni++)
            ldm4t(bh[ni], b_base + (ks*16*B2_ST + ni*16)*2);
#pragma unroll
        for (int mi = 0; mi < 2; mi++)
#pragma unroll
            for (int nj = 0; nj < 4; nj++)
                mma16816(acc[mi][nj], ah[mi], bh[nj>>1][2*(nj&1)], bh[nj>>1][2*(nj&1)+1]);
    }

    int rr = lane >> 2, cc = 2*(lane & 3);
#pragma unroll
    for (int mi = 0; mi < 2; mi++)
#pragma unroll
        for (int nj = 0; nj < 4; nj++){
            int col = n0 + nj*8 + cc;
            float bo0 = bos[col], bo1 = bos[col+1];
            float cw00 = cwos[0][col], cw01 = cwos[0][col+1];
            float cw10 = cwos[1][col], cw11 = cwos[1][col+1];
            float cw20 = cwos[2][col], cw21 = cwos[2][col+1];
            float cw30 = cwos[3][col], cw31 = cwos[3][col+1];
#pragma unroll
            for (int half = 0; half < 2; half++){
                int lrow = m0 + mi*16 + rr + half*8;
                float a0 = attns[lrow][0], a1 = attns[lrow][1];
                float a2 = attns[lrow][2], a3 = attns[lrow][3];
                float geo0 = a0*cw00 + a1*cw10 + a2*cw20 + a3*cw30;
                float geo1 = a0*cw01 + a1*cw11 + a2*cw21 + a3*cw31;
                float g = gsm[lrow];
                size_t off = (size_t)(tok0 + lrow)*DM + db + col;
                float2 xv = *(const float2*)(x + off);
                float2 o = make_float2(
                    g*(acc[mi][nj][2*half+0] + geo0 + bo0) + xv.x,
                    g*(acc[mi][nj][2*half+1] + geo1 + bo1) + xv.y);
                *(float2*)(out + off) = o;
            }
        }
}

// ---------------- scalars: ortho, temp mean, latent, geo ----------------
__global__ void k_final(const float* __restrict__ cent, float* __restrict__ dout){
    __shared__ float Kn[NC][DP];
    __shared__ float norms[NC];
    __shared__ float part[16];
    int tid = threadIdx.x;   // 64 threads
    if (tid < NC){
        float ss = 0.f;
        for (int d = 0; d < DP; d++){ float c = cent[tid*DP + d]; ss += c*c; }
        norms[tid] = fmaxf(sqrtf(ss), 1e-12f);
    }
    __syncthreads();
    if (tid < DP){
        for (int n = 0; n < NC; n++) Kn[n][tid] = cent[n*DP + tid] / norms[n];
    }
    __syncthreads();
    if (tid < 16){
        int i = tid >> 2, j = tid & 3;
        float dot = 0.f;
        for (int d = 0; d < DP; d++) dot += Kn[i][d]*Kn[j][d];
        float e2 = dot - (i == j ? 1.f : 0.f);
        part[tid] = e2*e2;
    }
    __syncthreads();
    if (tid == 0){
        float s = 0.f;
        for (int p = 0; p < 16; p++) s += part[p];
        dout[ORTHO_OFF] = s / 16.f;
        dout[TEMP_OFF] = g_temp_sum / (float)NTOK;
        dout[GEO_OFF] = 0.f;
        dout[LATENT_OFF] = 1.f - g_cos_sum / (float)NTOK;
    }
}

extern "C" void kernel_launch(void* const* d_in, const int* in_sizes, int n_in,
                              void* d_out, int out_size){
    const float* x    = (const float*)d_in[0];
    const float* Wp   = (const float*)d_in[1];
    const float* bp   = (const float*)d_in[2];
    const float* ln_g = (const float*)d_in[3];
    const float* ln_b = (const float*)d_in[4];
    const float* cent = (const float*)d_in[5];
    const float* Wo   = (const float*)d_in[6];
    const float* bo   = (const float*)d_in[7];
    const float* W1   = (const float*)d_in[8];
    const float* b1   = (const float*)d_in[9];
    const float* W2   = (const float*)d_in[10];
    const float* b2   = (const float*)d_in[11];
    const float* sl   = (const float*)d_in[12];
    const float* se   = (const float*)d_in[13];
    const float* tt   = (const float*)d_in[14];
    const float* ts   = (const float*)d_in[15];
    float* out = (float*)d_out;

    static int smem_set = 0;
    if (!smem_set){
        cudaFuncSetAttribute(k_gemm1tok, cudaFuncAttributeMaxDynamicSharedMemorySize, G1_SMEM_B);
        cudaFuncSetAttribute(k_gemm2, cudaFuncAttributeMaxDynamicSharedMemorySize, G2_SMEM_B);
        smem_set = 1;
    }

    // my launch index 3 = ncu's profiled slot (2 harness launches precede)
    k_stats<<<dim3(BB, NCHUNK), 256>>>(x);                   // 0
    k_finstats<<<64, 256>>>();                               // 1
    k_prewc<<<1108, 256>>>(Wp, bp, Wo, cent);                // 2
    k_gemm1tok<<<NTOK/128, 256, G1_SMEM_B>>>(x, cent, ln_g, ln_b, W1, b1, W2, b2,
                                             sl, se, tt, ts, out);  // 3 <-- profiled
    k_gemm2<<<dim3(DM/128, NTOK/128), 512, G2_SMEM_B>>>(x, bo, out, out);  // 4
    k_final<<<1, 64>>>(cent, out);                           // 5
}